// round 13
// baseline (speedup 1.0000x reference)
#include <cuda_runtime.h>

// FWHT, DIM=4096, fp32, scale 1/64. Three in-register H16 passes over bit
// groups {b0,b1,b10,b11} / {b2..b5} / {b6..b9}, two smem exchanges.
// 256 threads per CTA; each CTA processes TWO consecutive rows with both
// rows' global loads issued up front (register prefetch, MLP=8 LDG.128).
//
// I/O fully coalesced: loads 4x LDG.128 lane-contiguous per row, stores
// 16x STG.32 warp-contiguous (1 wavefront each). 768 L1 wavefronts/row
// (the provable minimum for this dataflow).
//
// Smem: 4096 words (16 KB). GF(2) swizzle P(e) = e ^ (b6<<2) ^ (b10<<3) ^ (b11<<4)
// -> bank bits (b0, b1, b2^b6, b3^b10, b4^b11). Verified conflict-free:
//   W1 STS.128: 8-lane phases vary b2b3b4 -> distinct 4-bank groups
//   P2 scalar:  lanes vary b0,b1,b6,b10,b11 -> bank bijective
//   P3 scalar:  lanes vary b0..b4 -> bank bijective
// Exchange 1 is warp-local (chunk bits 5..7 = warp id for both W1 writes and
// pass-2 reads) -> __syncwarp; exchange 2 crosses the CTA -> __syncthreads.

#define FWHT_DIM 4096

__device__ __forceinline__ void h16(float (&v)[16]) {
#pragma unroll
    for (int h = 1; h < 16; h <<= 1) {
#pragma unroll
        for (int i = 0; i < 16; i++) {
            if (!(i & h)) {
                float a = v[i];
                float b = v[i + h];
                v[i]     = a + b;
                v[i + h] = a - b;
            }
        }
    }
}

// v holds one row: v[4j+c] = element (j<<10)|(t<<2)|c. Runs all three passes
// and streams the scaled result to yr.
__device__ __forceinline__ void fwht_row(float (&v)[16], float* __restrict__ s,
                                         int t, float* __restrict__ yr) {
    h16(v);   // H16 over {b0,b1,b10,b11}

    // W1: 4x STS.128, swizzled chunk index (flips c0^=b6, c1^=b10, c2^=b11)
    {
        float4* s4 = reinterpret_cast<float4*>(s);
        const int tb = t ^ ((t >> 4) & 1);
#pragma unroll
        for (int j = 0; j < 4; j++) {
            int cj = (tb ^ ((j & 1) << 1) ^ ((j & 2) << 1)) + 256 * j;
            s4[cj] = make_float4(v[4 * j], v[4 * j + 1],
                                 v[4 * j + 2], v[4 * j + 3]);
        }
    }
    __syncwarp();   // exchange 1 is warp-local by construction

    // Pass 2: thread r owns b6=r&1, b0b1=(r>>1)&3, b10b11=(r>>3)&3, b7b8b9=r>>5
    {
        const int base = ((t >> 1) & 3) | ((t & 1) << 6) | ((t >> 5) << 7)
                       | (((t >> 3) & 3) << 10);
        const int sw = ((t & 1) << 2) | (((t >> 3) & 1) << 3)
                     | (((t >> 4) & 1) << 4);
#pragma unroll
        for (int m = 0; m < 16; m++)
            v[m] = s[base + ((4 * m) ^ sw)];

        h16(v);   // H16 over {b2..b5}

#pragma unroll
        for (int m = 0; m < 16; m++)
            s[base + ((4 * m) ^ sw)] = v[m];
    }
    __syncthreads();   // exchange 2 crosses the whole CTA

    // Pass 3: thread w owns b0..b5 = w&63, b10b11 = w>>6; regs k = b6..b9
    {
        const int basew = (t & 63) | ((t >> 6) << 10);
        const int swf = (((t >> 6) & 1) << 3) | (((t >> 7) & 1) << 4);
        const int pb = basew ^ swf;
#pragma unroll
        for (int k = 0; k < 16; k++)
            v[k] = s[(pb + 64 * k) ^ ((k & 1) << 2)];

        h16(v);   // H16 over {b6..b9}

        const float sc = 0.015625f;   // 1/64 = 1/sqrt(4096)
        float* __restrict__ yw = yr + basew;
#pragma unroll
        for (int k = 0; k < 16; k++)
            __stcs(yw + 64 * k, v[k] * sc);   // warp-contiguous, 1 wf each
    }
}

__global__ __launch_bounds__(256)
void fwht4096_kernel(const float* __restrict__ x, float* __restrict__ y) {
    __shared__ float s[4096];   // 16 KB, swizzled; reused for both rows

    const int t = threadIdx.x;                    // 0..255
    const size_t rowA = (size_t)blockIdx.x * (2 * FWHT_DIM);

    const float4* __restrict__ pA = reinterpret_cast<const float4*>(x + rowA);
    const float4* __restrict__ pB = pA + (FWHT_DIM / 4);

    // Issue BOTH rows' loads up front: 8 independent LDG.128 in flight.
    float4 a[4], b[4];
#pragma unroll
    for (int j = 0; j < 4; j++) a[j] = __ldcs(pA + t + 256 * j);
#pragma unroll
    for (int j = 0; j < 4; j++) b[j] = __ldcs(pB + t + 256 * j);

    float v[16];
#pragma unroll
    for (int j = 0; j < 4; j++) {
        v[4 * j + 0] = a[j].x; v[4 * j + 1] = a[j].y;
        v[4 * j + 2] = a[j].z; v[4 * j + 3] = a[j].w;
    }
    fwht_row(v, s, t, y + rowA);

    __syncthreads();   // pass-3(A) smem reads complete before W1(B) overwrites

#pragma unroll
    for (int j = 0; j < 4; j++) {
        v[4 * j + 0] = b[j].x; v[4 * j + 1] = b[j].y;
        v[4 * j + 2] = b[j].z; v[4 * j + 3] = b[j].w;
    }
    fwht_row(v, s, t, y + rowA + FWHT_DIM);
}

extern "C" void kernel_launch(void* const* d_in, const int* in_sizes, int n_in,
                              void* d_out, int out_size) {
    (void)n_in; (void)out_size;
    const float* x = (const float*)d_in[0];
    float* y = (float*)d_out;
    const int rows = in_sizes[0] / FWHT_DIM;   // 16384
    fwht4096_kernel<<<rows / 2, 256>>>(x, y);
}

// round 14
// speedup vs baseline: 1.0181x; 1.0181x over previous
#include <cuda_runtime.h>

// FWHT, DIM=4096, fp32, scale 1/64. Three in-register H16 passes over bit
// groups {b0,b1,b10,b11} / {b2..b5} / {b6..b9}, two smem exchanges.
// One CTA (256 threads) per row, 16 floats/thread. 768 L1 wavefronts/row
// (provable minimum for this dataflow); kernel runs at the mixed-R/W DRAM
// ceiling (~6.2 TB/s), so the structure is chosen for minimal overhead.
//
// I/O fully coalesced: loads 4x LDG.128 lane-contiguous, stores 16x STG.32
// warp-contiguous (1 wavefront each).
//
// Smem: 4096 words (16 KB). GF(2) swizzle P(e) = e ^ (b6<<2) ^ (b10<<3) ^ (b11<<4)
// -> bank bits (b0, b1, b2^b6, b3^b10, b4^b11). Verified conflict-free:
//   W1 STS.128: 8-lane phases vary b2b3b4 -> distinct 4-bank groups
//   P2 scalar:  lanes vary b0,b1,b6,b10,b11 -> bank bijective
//   P3 scalar:  lanes vary b0..b4 -> bank bijective
// Exchange 1 is warp-local (chunk bits 5..7 equal the warp id for both the
// W1 writes and the pass-2 reads) -> __syncwarp; exchange 2 crosses the CTA
// -> __syncthreads. One full barrier per row total.

#define FWHT_DIM 4096

__device__ __forceinline__ void h16(float (&v)[16]) {
#pragma unroll
    for (int h = 1; h < 16; h <<= 1) {
#pragma unroll
        for (int i = 0; i < 16; i++) {
            if (!(i & h)) {
                float a = v[i];
                float b = v[i + h];
                v[i]     = a + b;
                v[i + h] = a - b;
            }
        }
    }
}

__global__ __launch_bounds__(256)
void fwht4096_kernel(const float* __restrict__ x, float* __restrict__ y) {
    __shared__ float s[4096];   // 16 KB, swizzled

    const int t = threadIdx.x;                    // 0..255
    const size_t row = (size_t)blockIdx.x * FWHT_DIM;

    float v[16];

    // ---- Load: lane-contiguous LDG.128. v[4j+c] = element (j<<10)|(t<<2)|c
    //      regs own {b0,b1,b10,b11}; lanes own b2..b9 (= t). ----
    {
        const float4* __restrict__ p = reinterpret_cast<const float4*>(x + row);
#pragma unroll
        for (int j = 0; j < 4; j++) {
            float4 f = __ldcs(p + t + 256 * j);
            v[4 * j + 0] = f.x;
            v[4 * j + 1] = f.y;
            v[4 * j + 2] = f.z;
            v[4 * j + 3] = f.w;
        }
    }

    h16(v);   // H16 over {b0,b1,b10,b11}

    // ---- W1: 4x STS.128. Chunk c = t + 256j; swizzled chunk flips
    //      c0^=b6, c1^=b10, c2^=b11. ----
    {
        float4* s4 = reinterpret_cast<float4*>(s);
        const int tb = t ^ ((t >> 4) & 1);          // fold b6 into chunk bit 0
#pragma unroll
        for (int j = 0; j < 4; j++) {
            int cj = (tb ^ ((j & 1) << 1) ^ ((j & 2) << 1)) + 256 * j;
            s4[cj] = make_float4(v[4 * j], v[4 * j + 1],
                                 v[4 * j + 2], v[4 * j + 3]);
        }
    }
    __syncwarp();   // exchange 1 is warp-local by construction

    // ---- Pass 2: thread r owns b6=r&1, b0b1=(r>>1)&3, b10b11=(r>>3)&3,
    //      b7b8b9=r>>5; regs m = b2..b5.
    //      addr = base + ((4m) ^ sw), sw = (b6<<2)|(b10<<3)|(b11<<4). ----
    {
        const int base = ((t >> 1) & 3) | ((t & 1) << 6) | ((t >> 5) << 7)
                       | (((t >> 3) & 3) << 10);
        const int sw = ((t & 1) << 2) | (((t >> 3) & 1) << 3)
                     | (((t >> 4) & 1) << 4);
#pragma unroll
        for (int m = 0; m < 16; m++)
            v[m] = s[base + ((4 * m) ^ sw)];

        h16(v);   // H16 over {b2..b5}

#pragma unroll
        for (int m = 0; m < 16; m++)
            s[base + ((4 * m) ^ sw)] = v[m];
    }
    __syncthreads();   // exchange 2 crosses the whole CTA

    // ---- Pass 3: thread w owns b0..b5 = w&63, b10b11 = w>>6; regs k = b6..b9.
    //      addr = ((basew ^ swf) + 64k) ^ ((k&1)<<2). ----
    {
        const int basew = (t & 63) | ((t >> 6) << 10);
        const int swf = (((t >> 6) & 1) << 3) | (((t >> 7) & 1) << 4);
        const int pb = basew ^ swf;
#pragma unroll
        for (int k = 0; k < 16; k++)
            v[k] = s[(pb + 64 * k) ^ ((k & 1) << 2)];

        h16(v);   // H16 over {b6..b9}

        const float sc = 0.015625f;   // 1/64 = 1/sqrt(4096)
        float* __restrict__ yr = y + row + basew;
#pragma unroll
        for (int k = 0; k < 16; k++)
            __stcs(yr + 64 * k, v[k] * sc);   // warp-contiguous, 1 wf each
    }
}

extern "C" void kernel_launch(void* const* d_in, const int* in_sizes, int n_in,
                              void* d_out, int out_size) {
    (void)n_in; (void)out_size;
    const float* x = (const float*)d_in[0];
    float* y = (float*)d_out;
    const int rows = in_sizes[0] / FWHT_DIM;   // 16384
    fwht4096_kernel<<<rows, 256>>>(x, y);
}